// round 1
// baseline (speedup 1.0000x reference)
#include <cuda_runtime.h>
#include <math.h>

// Problem shape (fixed for this dataset)
#define BB 8
#define NN 2048
#define MM 2048
#define DD 256

// GEMM tiling
#define BN 128
#define BM 128
#define BK 16
#define SST 132   // padded shared stride (floats)

// Scratch: inverse norms
__device__ float g_invx[BB * NN];
__device__ float g_invy[BB * MM];

// ---------------------------------------------------------------------------
// Kernel 1: per-row inverse L2 norms for src and dst descriptors.
// One warp per row (256 floats = 2 float4 per lane).
// ---------------------------------------------------------------------------
__global__ void norms_kernel(const float* __restrict__ src,
                             const float* __restrict__ dst) {
    int gwarp = (blockIdx.x * blockDim.x + threadIdx.x) >> 5;
    int lane  = threadIdx.x & 31;
    const int total = BB * NN + BB * MM;
    if (gwarp >= total) return;

    const float* p;
    float* outp;
    if (gwarp < BB * NN) {
        p = src + (size_t)gwarp * DD;
        outp = &g_invx[gwarp];
    } else {
        int r = gwarp - BB * NN;
        p = dst + (size_t)r * DD;
        outp = &g_invy[r];
    }
    const float4* p4 = (const float4*)p;
    float4 v0 = p4[lane];
    float4 v1 = p4[lane + 32];
    float s = v0.x * v0.x + v0.y * v0.y + v0.z * v0.z + v0.w * v0.w
            + v1.x * v1.x + v1.y * v1.y + v1.z * v1.z + v1.w * v1.w;
#pragma unroll
    for (int o = 16; o > 0; o >>= 1)
        s += __shfl_xor_sync(0xffffffffu, s, o);
    if (lane == 0) {
        float nrm = sqrtf(s);
        // EPS clamp from reference (norms are ~16 so this never binds, but be exact-ish)
        *outp = 1.0f / fmaxf(nrm, 1e-12f);
    }
}

// ---------------------------------------------------------------------------
// Kernel 2: fused cosine-sim GEMM + running argmax over M + gather epilogue.
// Block: 256 threads = 16x16, 8x8 register tile -> 128(N) x 128(M) tile.
// Each block owns 128 src rows of one batch and sweeps all M, so the
// (max, argmax) lives entirely in registers until the epilogue.
// ---------------------------------------------------------------------------
__global__ __launch_bounds__(256, 2)
void match_kernel(const float* __restrict__ A,      // [B,N,D] src
                  const float* __restrict__ Bd,     // [B,M,D] dst
                  const float* __restrict__ pts,    // [B,M,2]
                  float* __restrict__ out) {        // [B*N*2 matched | B*N conf]
    __shared__ float As[BK * SST];
    __shared__ float Bs[BK * SST];

    const int b  = blockIdx.y;
    const int n0 = blockIdx.x * BN;
    const int tid = threadIdx.x;
    const int tx = tid & 15;
    const int ty = tid >> 4;

    const float* Ab = A  + (size_t)b * NN * DD;
    const float* Bb = Bd + (size_t)b * MM * DD;
    const float* invy_b = &g_invy[b * MM];

    float best[8];
    int   bidx[8];
#pragma unroll
    for (int i = 0; i < 8; i++) { best[i] = -1e30f; bidx[i] = 0; }

    // Tile-load index precompute: each thread moves 2 float4 per matrix.
    const int f0  = tid;
    const int an0 = f0 >> 2;          // tile row 0..63
    const int ac0 = (f0 & 3) * 4;     // k offset 0,4,8,12
    const int f1  = tid + 256;
    const int an1 = f1 >> 2;          // tile row 64..127
    const int ac1 = (f1 & 3) * 4;

    for (int mt = 0; mt < MM; mt += BM) {
        float acc[8][8];
#pragma unroll
        for (int i = 0; i < 8; i++)
#pragma unroll
            for (int j = 0; j < 8; j++) acc[i][j] = 0.0f;

        for (int kt = 0; kt < DD; kt += BK) {
            float4 a0v = *(const float4*)(Ab + (size_t)(n0 + an0) * DD + kt + ac0);
            float4 a1v = *(const float4*)(Ab + (size_t)(n0 + an1) * DD + kt + ac1);
            float4 b0v = *(const float4*)(Bb + (size_t)(mt + an0) * DD + kt + ac0);
            float4 b1v = *(const float4*)(Bb + (size_t)(mt + an1) * DD + kt + ac1);

            __syncthreads();   // previous iter's smem reads complete
            As[(ac0 + 0) * SST + an0] = a0v.x;
            As[(ac0 + 1) * SST + an0] = a0v.y;
            As[(ac0 + 2) * SST + an0] = a0v.z;
            As[(ac0 + 3) * SST + an0] = a0v.w;
            As[(ac1 + 0) * SST + an1] = a1v.x;
            As[(ac1 + 1) * SST + an1] = a1v.y;
            As[(ac1 + 2) * SST + an1] = a1v.z;
            As[(ac1 + 3) * SST + an1] = a1v.w;
            Bs[(ac0 + 0) * SST + an0] = b0v.x;
            Bs[(ac0 + 1) * SST + an0] = b0v.y;
            Bs[(ac0 + 2) * SST + an0] = b0v.z;
            Bs[(ac0 + 3) * SST + an0] = b0v.w;
            Bs[(ac1 + 0) * SST + an1] = b1v.x;
            Bs[(ac1 + 1) * SST + an1] = b1v.y;
            Bs[(ac1 + 2) * SST + an1] = b1v.z;
            Bs[(ac1 + 3) * SST + an1] = b1v.w;
            __syncthreads();

#pragma unroll
            for (int k = 0; k < BK; k++) {
                float4 a0 = *(const float4*)&As[k * SST + 8 * ty];
                float4 a1 = *(const float4*)&As[k * SST + 8 * ty + 4];
                float4 c0 = *(const float4*)&Bs[k * SST + 8 * tx];
                float4 c1 = *(const float4*)&Bs[k * SST + 8 * tx + 4];
                float av[8] = {a0.x, a0.y, a0.z, a0.w, a1.x, a1.y, a1.z, a1.w};
                float bv[8] = {c0.x, c0.y, c0.z, c0.w, c1.x, c1.y, c1.z, c1.w};
#pragma unroll
                for (int i = 0; i < 8; i++)
#pragma unroll
                    for (int j = 0; j < 8; j++)
                        acc[i][j] = fmaf(av[i], bv[j], acc[i][j]);
            }
        }

        // Fold this M-tile into the running per-row argmax.
#pragma unroll
        for (int j = 0; j < 8; j++) {
            const int m = mt + 8 * tx + j;
            const float iv = __ldg(&invy_b[m]);
#pragma unroll
            for (int i = 0; i < 8; i++) {
                float t = acc[i][j] * iv;
                if (t > best[i]) { best[i] = t; bidx[i] = m; }   // strict > : first max wins
            }
        }
    }

    // Cross-lane reduce over tx (lanes 0-15 / 16-31 are independent halves;
    // xor strides < 16 never cross halves).
#pragma unroll
    for (int s = 1; s < 16; s <<= 1) {
#pragma unroll
        for (int i = 0; i < 8; i++) {
            float ov = __shfl_xor_sync(0xffffffffu, best[i], s);
            int   oi = __shfl_xor_sync(0xffffffffu, bidx[i], s);
            if (ov > best[i] || (ov == best[i] && oi < bidx[i])) {
                best[i] = ov; bidx[i] = oi;
            }
        }
    }

    if (tx == 0) {
#pragma unroll
        for (int i = 0; i < 8; i++) {
            const int n  = n0 + 8 * ty + i;
            const int gi = b * NN + n;
            out[(size_t)BB * NN * 2 + gi] = best[i] * g_invx[gi];  // confidence
            const float* pp = pts + ((size_t)b * MM + bidx[i]) * 2;
            out[(size_t)gi * 2 + 0] = pp[0];                        // matched x
            out[(size_t)gi * 2 + 1] = pp[1];                        // matched y
        }
    }
}

// ---------------------------------------------------------------------------
extern "C" void kernel_launch(void* const* d_in, const int* in_sizes, int n_in,
                              void* d_out, int out_size) {
    const float* desc_src   = (const float*)d_in[0];
    const float* desc_dst   = (const float*)d_in[1];
    const float* points_dst = (const float*)d_in[2];
    float* out = (float*)d_out;

    // Norms: one warp per row, 8 warps per block.
    const int total_rows = BB * NN + BB * MM;
    norms_kernel<<<(total_rows + 7) / 8, 256>>>(desc_src, desc_dst);

    dim3 grid(NN / BN, BB);
    match_kernel<<<grid, 256>>>(desc_src, desc_dst, points_dst, out);
}